// round 15
// baseline (speedup 1.0000x reference)
#include <cuda_runtime.h>
#include <math.h>

// Problem constants (fixed shapes: z = (16, 128, 64, 64) fp32, codebook = (1024, 128) fp32)
#define CDIM    128
#define KCODES  1024
#define HWDIM   4096          // 64*64 pixels per batch image
#define NPIXMAX 65536         // 16 * 4096
#define PBLOCKS 1024          // quant partial blocks

// ---- scratch (no allocations allowed; __device__ globals are the sanctioned path) ----
__device__ float  g_zz[NPIXMAX];         // per-pixel sum(z^2), sequential fp32
__device__ float  g_ee[KCODES];          // per-code sum(e^2), sequential fp32
__device__ int    g_idx[NPIXMAX];        // argmin indices
__device__ int    g_counts[KCODES];      // code histogram
__device__ double g_partials[PBLOCKS];   // deterministic per-block loss partials
__device__ float  g_idx_scratch[NPIXMAX];// fallback index sink if out buffer too small

// ---- packed fp32x2 helpers (lanewise IEEE fp32 => numerics identical to scalar) ----
__device__ __forceinline__ unsigned long long dup_f32(float x) {
    unsigned long long r;
    asm("mov.b64 %0, {%1, %1};" : "=l"(r) : "f"(x));
    return r;
}
__device__ __forceinline__ void fma_f32x2(unsigned long long& d,
                                          unsigned long long a,
                                          unsigned long long b) {
    asm("fma.rn.f32x2 %0, %1, %2, %3;" : "=l"(d) : "l"(a), "l"(b), "l"(d));
}
__device__ __forceinline__ void unpack_f32x2(float& lo, float& hi, unsigned long long v) {
    asm("mov.b64 {%0, %1}, %2;" : "=f"(lo), "=f"(hi) : "l"(v));
}

// ------------------------------------------------------------------
__global__ void zero_counts_kernel() {
    int i = blockIdx.x * blockDim.x + threadIdx.x;
    if (i < KCODES) g_counts[i] = 0;
}

// ------------------------------------------------------------------
// zz[n] = sum_c fl(z[b,c,hw]^2), strictly sequential fp32 adds
// ------------------------------------------------------------------
__global__ void zz_kernel(const float* __restrict__ z, int npix) {
    int n = blockIdx.x * blockDim.x + threadIdx.x;
    if (n >= npix) return;
    int b  = n / HWDIM;
    int hw = n - b * HWDIM;
    const float* p = z + ((size_t)b * CDIM) * HWDIM + hw;
    float s = 0.0f;
#pragma unroll
    for (int c = 0; c < CDIM; c++) {
        float v = p[(size_t)c * HWDIM];
        s = __fadd_rn(s, __fmul_rn(v, v));   // no FMA, no reassociation
    }
    g_zz[n] = s;
}

// ------------------------------------------------------------------
__global__ void ee_kernel(const float* __restrict__ cb) {
    int k = blockIdx.x * blockDim.x + threadIdx.x;
    if (k >= KCODES) return;
    const float* p = cb + (size_t)k * CDIM;
    float s = 0.0f;
#pragma unroll
    for (int c = 0; c < CDIM; c++) {
        float v = p[c];
        s = __fadd_rn(s, __fmul_rn(v, v));
    }
    g_ee[k] = s;
}

// ------------------------------------------------------------------
// argmin R11 (re-bench; R14 was an infra failure, kernel never ran):
// R9's exact compute micro-loop (pixel pairs in f32x2 lanes, es float4
// per 4 codes) with two structural changes:
//  (a) z tile (64 px x 128 c = 32KB) resident in smem, loaded ONCE in
//      the prologue -> no per-chunk z LDG/STS (R9 re-streamed z 8x).
//  (b) chunks are 16 c wide -> 64 barriers instead of 128; es double-
//      buffered (2 x 16c x 128 codes) with register staging at
//      distance 2 (store g+1 from regs, LDG g+2, compute g, ONE bar).
// Accumulation per (pixel,code): sequential ascending-c fp32 FMA chain
// carried across the 8 chunks of each 128-code tile (bit-identical to
// R1-R10: rel_err must remain 3.874629e-07).
// d2 = fl(fl(zz - fl(2*dot)) + ee); first-minimum (lowest k) tie-break.
// ------------------------------------------------------------------
__global__ void __launch_bounds__(256) argmin_kernel(
        const float* __restrict__ z, const float* __restrict__ cb) {
    __shared__ __align__(16) float zs[CDIM][64];     // [c][pixel]     32KB, once
    __shared__ __align__(16) float es[2][16][132];   // [buf][ci][code] 16.5KB padded
    __shared__ float ees[KCODES];                    // cached code norms 4KB

    const int tid  = threadIdx.x;
    const int lane = tid & 31;
    const int tp   = tid >> 5;

    const int n0  = blockIdx.x * 64;        // 4096 % 64 == 0 -> tile never straddles b
    const int b   = n0 >> 12;
    const int hw0 = n0 & (HWDIM - 1);
    const float* zbase = z + ((size_t)b * CDIM) * HWDIM + hw0;

    // es loader geometry: thread covers code kk, c-halves h..h+7 of a 16-c chunk
    const int kk = tid >> 1;                // code 0..127 within tile
    const int h  = (tid & 1) * 8;           // c-offset within chunk (0 or 8)

    float zzr[8];
#pragma unroll
    for (int pp = 0; pp < 8; pp++) zzr[pp] = g_zz[n0 + tp * 8 + pp];

    float bestv[8];
    int   besti[8];
#pragma unroll
    for (int pp = 0; pp < 8; pp++) { bestv[pp] = 3.4e38f; besti[pp] = 0x7fffffff; }

    // ---- prologue ----
    // z tile: 128 rows x 64 floats, float4-coalesced, loaded once
#pragma unroll
    for (int pass = 0; pass < 8; pass++) {
        int r = (tid >> 4) + pass * 16;
        int q = (tid & 15) * 4;
        *(float4*)&zs[r][q] = *(const float4*)(zbase + (size_t)r * HWDIM + q);
    }
    // chunk 0 (kt=0, c 0..15) into regs
    float4 cbv0 = *(const float4*)(cb + (size_t)kk * CDIM + h);
    float4 cbv1 = *(const float4*)(cb + (size_t)kk * CDIM + h + 4);
    // ee cache (independent loads cover latency)
#pragma unroll
    for (int i = 0; i < KCODES / 256; i++) ees[tid + i * 256] = g_ee[tid + i * 256];
    // store chunk 0 -> buffer 0 (one-time exposed latency)
    es[0][h + 0][kk] = cbv0.x; es[0][h + 1][kk] = cbv0.y;
    es[0][h + 2][kk] = cbv0.z; es[0][h + 3][kk] = cbv0.w;
    es[0][h + 4][kk] = cbv1.x; es[0][h + 5][kk] = cbv1.y;
    es[0][h + 6][kk] = cbv1.z; es[0][h + 7][kk] = cbv1.w;
    // stage chunk 1 (kt=0, c 16..31)
    cbv0 = *(const float4*)(cb + (size_t)kk * CDIM + 16 + h);
    cbv1 = *(const float4*)(cb + (size_t)kk * CDIM + 16 + h + 4);
    __syncthreads();                        // zs + es[0] + ees visible

    unsigned long long acc[4][4];           // [pixel pair][code j]
#pragma unroll
    for (int pq = 0; pq < 4; pq++)
#pragma unroll
        for (int j = 0; j < 4; j++) acc[pq][j] = 0ull;

    // chunk g: kt = g>>3 (128-code tile), c0 = (g&7)*16
#pragma unroll 1
    for (int g = 0; g < 64; g++) {
        const int buf = g & 1;
        // (1) store chunk g+1 from staged regs (data already arrived);
        //     readers of buf^1 passed the barrier ending iter g-1
        if (g + 1 < 64) {
            const int nb = 1 - buf;
            es[nb][h + 0][kk] = cbv0.x; es[nb][h + 1][kk] = cbv0.y;
            es[nb][h + 2][kk] = cbv0.z; es[nb][h + 3][kk] = cbv0.w;
            es[nb][h + 4][kk] = cbv1.x; es[nb][h + 5][kk] = cbv1.y;
            es[nb][h + 6][kk] = cbv1.z; es[nb][h + 7][kk] = cbv1.w;
        }
        // (2) issue LDG for chunk g+2 (covered by this iteration's compute)
        if (g + 2 < 64) {
            const int g2 = g + 2;
            const float* src =
                cb + (size_t)((g2 >> 3) * 128 + kk) * CDIM + (g2 & 7) * 16 + h;
            cbv0 = *(const float4*)(src + 0);
            cbv1 = *(const float4*)(src + 4);
        }
        // (3) compute the 16 c-slices of chunk g (micro-loop == R9)
        const int c0 = (g & 7) * 16;
#pragma unroll
        for (int ci = 0; ci < 16; ci++) {
            const int c = c0 + ci;
            ulonglong2 zlo = *(const ulonglong2*)&zs[c][tp * 8];      // broadcast
            ulonglong2 zhi = *(const ulonglong2*)&zs[c][tp * 8 + 4];  // broadcast
            float4 er = *(const float4*)&es[buf][ci][lane * 4];       // conflict-free
            unsigned long long e0 = dup_f32(er.x);
            unsigned long long e1 = dup_f32(er.y);
            unsigned long long e2 = dup_f32(er.z);
            unsigned long long e3 = dup_f32(er.w);
            fma_f32x2(acc[0][0], zlo.x, e0); fma_f32x2(acc[0][1], zlo.x, e1);
            fma_f32x2(acc[0][2], zlo.x, e2); fma_f32x2(acc[0][3], zlo.x, e3);
            fma_f32x2(acc[1][0], zlo.y, e0); fma_f32x2(acc[1][1], zlo.y, e1);
            fma_f32x2(acc[1][2], zlo.y, e2); fma_f32x2(acc[1][3], zlo.y, e3);
            fma_f32x2(acc[2][0], zhi.x, e0); fma_f32x2(acc[2][1], zhi.x, e1);
            fma_f32x2(acc[2][2], zhi.x, e2); fma_f32x2(acc[2][3], zhi.x, e3);
            fma_f32x2(acc[3][0], zhi.y, e0); fma_f32x2(acc[3][1], zhi.y, e1);
            fma_f32x2(acc[3][2], zhi.y, e2); fma_f32x2(acc[3][3], zhi.y, e3);
        }
        // (4) end of a 128-code tile? score + reset accumulators
        if ((g & 7) == 7) {
            const int kt = g >> 3;
#pragma unroll
            for (int j = 0; j < 4; j++) {
                int k = kt * 128 + lane * 4 + j;
                float ee = ees[k];
#pragma unroll
                for (int pq = 0; pq < 4; pq++) {
                    float dlo, dhi;
                    unpack_f32x2(dlo, dhi, acc[pq][j]);
                    float d2lo = __fadd_rn(__fsub_rn(zzr[2 * pq + 0], __fmul_rn(2.0f, dlo)), ee);
                    float d2hi = __fadd_rn(__fsub_rn(zzr[2 * pq + 1], __fmul_rn(2.0f, dhi)), ee);
                    if (d2lo < bestv[2 * pq + 0]) { bestv[2 * pq + 0] = d2lo; besti[2 * pq + 0] = k; }
                    if (d2hi < bestv[2 * pq + 1]) { bestv[2 * pq + 1] = d2hi; besti[2 * pq + 1] = k; }
                    acc[pq][j] = 0ull;
                }
            }
        }
        __syncthreads();   // single barrier per 16-c chunk (64 total)
    }

    // warp reduction; tie -> smaller index (jnp.argmin first-occurrence)
#pragma unroll
    for (int off = 16; off > 0; off >>= 1) {
#pragma unroll
        for (int pp = 0; pp < 8; pp++) {
            float ov = __shfl_down_sync(0xffffffffu, bestv[pp], off);
            int   oi = __shfl_down_sync(0xffffffffu, besti[pp], off);
            if (ov < bestv[pp] || (ov == bestv[pp] && oi < besti[pp])) {
                bestv[pp] = ov; besti[pp] = oi;
            }
        }
    }
    if (lane == 0) {
#pragma unroll
        for (int pp = 0; pp < 8; pp++) g_idx[n0 + tp * 8 + pp] = besti[pp];
    }
}

// ------------------------------------------------------------------
// gather + straight-through output + deterministic loss partials.
// ------------------------------------------------------------------
__global__ void __launch_bounds__(256) quant_kernel(
        const float* __restrict__ z, const float* __restrict__ cb,
        float* __restrict__ outq, int total) {
    __shared__ double sh[8];
    double sq = 0.0;
    const int stride = gridDim.x * blockDim.x * 4;
    int total4 = total & ~3;
    for (int base = (blockIdx.x * blockDim.x + threadIdx.x) * 4; base < total4;
         base += stride) {
        float4 zv = *(const float4*)(z + base);
        int hw = base & (HWDIM - 1);            // 4 elems stay in one (b,c) row
        int c  = (base >> 12) & (CDIM - 1);
        int b  = base >> 19;
        int n  = b * HWDIM + hw;
        float q0 = cb[(size_t)g_idx[n + 0] * CDIM + c];
        float q1 = cb[(size_t)g_idx[n + 1] * CDIM + c];
        float q2 = cb[(size_t)g_idx[n + 2] * CDIM + c];
        float q3 = cb[(size_t)g_idx[n + 3] * CDIM + c];
        float4 o;
        o.x = __fadd_rn(zv.x, __fsub_rn(q0, zv.x));   // exact STE rounding
        o.y = __fadd_rn(zv.y, __fsub_rn(q1, zv.y));
        o.z = __fadd_rn(zv.z, __fsub_rn(q2, zv.z));
        o.w = __fadd_rn(zv.w, __fsub_rn(q3, zv.w));
        *(float4*)(outq + base) = o;
        float d0 = __fsub_rn(zv.x, q0), d1 = __fsub_rn(zv.y, q1);
        float d2 = __fsub_rn(zv.z, q2), d3 = __fsub_rn(zv.w, q3);
        sq += (double)__fmul_rn(d0, d0);
        sq += (double)__fmul_rn(d1, d1);
        sq += (double)__fmul_rn(d2, d2);
        sq += (double)__fmul_rn(d3, d3);
    }
    for (int i = total4 + blockIdx.x * blockDim.x + threadIdx.x; i < total;
         i += gridDim.x * blockDim.x) {
        int hw = i & (HWDIM - 1);
        int c  = (i >> 12) & (CDIM - 1);
        int b  = i >> 19;
        int k  = g_idx[b * HWDIM + hw];
        float zv = z[i];
        float q  = cb[(size_t)k * CDIM + c];
        outq[i]  = __fadd_rn(zv, __fsub_rn(q, zv));
        float d  = __fsub_rn(zv, q);
        sq += (double)__fmul_rn(d, d);
    }
#pragma unroll
    for (int off = 16; off > 0; off >>= 1)
        sq += __shfl_down_sync(0xffffffffu, sq, off);
    int warp = threadIdx.x >> 5;
    if ((threadIdx.x & 31) == 0) sh[warp] = sq;
    __syncthreads();
    if (threadIdx.x == 0) {
        double s = 0.0;
        for (int w = 0; w < 8; w++) s += sh[w];   // fixed order -> deterministic
        g_partials[blockIdx.x] = s;
    }
}

// ------------------------------------------------------------------
__global__ void hist_kernel(float* __restrict__ idx_out, int npix, int write_out) {
    __shared__ int h[KCODES];
    float* dst = write_out ? idx_out : g_idx_scratch;
    for (int i = threadIdx.x; i < KCODES; i += blockDim.x) h[i] = 0;
    __syncthreads();
    for (int n = blockIdx.x * blockDim.x + threadIdx.x; n < npix;
         n += gridDim.x * blockDim.x) {
        int k = g_idx[n];
        atomicAdd(&h[k], 1);
        dst[n] = (float)k;
    }
    __syncthreads();
    for (int i = threadIdx.x; i < KCODES; i += blockDim.x)
        if (h[i]) atomicAdd(&g_counts[i], h[i]);
}

// ------------------------------------------------------------------
__global__ void finalize_kernel(float* __restrict__ out2, int nblocks,
                                double inv_total, int npix) {
    __shared__ double sh[256];
    __shared__ double sh2[256];
    double s = 0.0;
    for (int i = threadIdx.x; i < nblocks; i += 256) s += g_partials[i];
    double h = 0.0;
    double inv_n = 1.0 / (double)npix;
    for (int k = threadIdx.x; k < KCODES; k += 256) {
        double p = (double)g_counts[k] * inv_n;
        h -= p * log(p + 1e-10);
    }
    sh[threadIdx.x]  = s;
    sh2[threadIdx.x] = h;
    __syncthreads();
    for (int st = 128; st > 0; st >>= 1) {
        if (threadIdx.x < st) {
            sh[threadIdx.x]  += sh[threadIdx.x + st];
            sh2[threadIdx.x] += sh2[threadIdx.x + st];
        }
        __syncthreads();
    }
    if (threadIdx.x == 0) {
        double mse = sh[0] * inv_total;
        float m  = (float)mse;
        out2[0] = __fadd_rn(m, __fmul_rn(0.25f, m));
        out2[1] = (float)exp(sh2[0]);
    }
}

// ------------------------------------------------------------------
// Output layout (all float32): [quantized (total) | indices (npix) |
// vq_loss (1) | perplexity (1)] — guarded by out_size.
// ------------------------------------------------------------------
extern "C" void kernel_launch(void* const* d_in, const int* in_sizes, int n_in,
                              void* d_out, int out_size) {
    const float* z  = (const float*)d_in[0];
    const float* cb = (const float*)d_in[1];
    float* out = (float*)d_out;

    int total = in_sizes[0];          // 8388608
    int npix  = total / CDIM;         // 65536

    zero_counts_kernel<<<(KCODES + 255) / 256, 256>>>();
    zz_kernel<<<(npix + 255) / 256, 256>>>(z, npix);
    ee_kernel<<<(KCODES + 255) / 256, 256>>>(cb);
    argmin_kernel<<<npix / 64, 256>>>(z, cb);
    quant_kernel<<<PBLOCKS, 256>>>(z, cb, out, total);

    int write_idx = (out_size >= total + npix) ? 1 : 0;
    hist_kernel<<<64, 256>>>(out + total, npix, write_idx);

    if (out_size >= total + npix + 2) {
        finalize_kernel<<<1, 256>>>(out + total + npix, PBLOCKS,
                                    1.0 / (double)total, npix);
    }
    (void)n_in;
}